// round 8
// baseline (speedup 1.0000x reference)
#include <cuda_runtime.h>
#include <math.h>

// Problem constants
#define NROWS 4096
#define DDIM  1024

// Scratch (device-global: no allocation allowed in kernel_launch).
// __align__(16): these are accessed with float4 (128-bit) loads/stores, and the
// language only guarantees element alignment for plain arrays.
__device__ __align__(16) float g_Q[NROWS * DDIM];
__device__ __align__(16) float g_K[NROWS * DDIM];
__device__ __align__(16) float g_V[NROWS * DDIM];
__device__ __align__(16) float g_S[(size_t)NROWS * NROWS];

// ---------------------------------------------------------------------------
// Packed fp32x2 helpers (Blackwell dual-rate fp32; ptxas never auto-emits)
// ---------------------------------------------------------------------------
__device__ __forceinline__ unsigned long long pack_dup(float a) {
    unsigned long long r;
    asm("mov.b64 %0, {%1, %1};" : "=l"(r) : "f"(a));
    return r;
}
__device__ __forceinline__ void ffma2(unsigned long long& c,
                                      unsigned long long a,
                                      unsigned long long b) {
    asm("fma.rn.f32x2 %0, %1, %2, %0;" : "+l"(c) : "l"(a), "l"(b));
}

// ---------------------------------------------------------------------------
// Tiled SGEMM: C[M,N] = cScale * (A[M,K] * B)
//   (B is [K,N] if !TRANSB, [N,K] if TRANSB)
// BM=BN=128, BK=16, 256 threads, 8x8 per thread, f32x2 inner product.
// Double-buffered SMEM (ping-pong): ONE barrier per k-tile. Register prefetch
// of the next tile overlaps global latency with ~2048 cycles of FMA per tile.
// MULTI=true: blockIdx.z in {0,1,2} selects (B,C) pair -> fused QKV launch.
// All dims are multiples of 128 (4096 / 1024), so no bounds checks.
// ---------------------------------------------------------------------------
template <bool TRANSB, bool MULTI>
__global__ __launch_bounds__(256, 2) void sgemm_kernel(
    const float* __restrict__ A,
    const float* __restrict__ B0,
    const float* __restrict__ B1,
    const float* __restrict__ B2,
    float* __restrict__ C0,
    float* __restrict__ C1,
    float* __restrict__ C2,
    int M, int N, int K, float cScale)
{
    constexpr int BM = 128, BN = 128, BK = 16;
    __shared__ __align__(16) float As[2][BK][BM];
    __shared__ __align__(16) float Bs[2][BK][BN];

    const float* B = B0;
    float*       C = C0;
    if (MULTI) {
        if (blockIdx.z == 1) { B = B1; C = C1; }
        else if (blockIdx.z == 2) { B = B2; C = C2; }
    }

    const int t  = threadIdx.x;
    const int tx = t & 15;        // 0..15  -> n direction
    const int ty = t >> 4;        // 0..15  -> m direction
    const int mBase = blockIdx.y * BM;
    const int nBase = blockIdx.x * BN;

    // Per-thread staging addresses (constant across k-tiles except k offset)
    const int aRow0 = t >> 2;                 // 0..63
    const int aRow1 = aRow0 + 64;             // 64..127
    const int aK    = (t & 3) * 4;            // 0,4,8,12
    const float* aPtr0 = &A[(size_t)(mBase + aRow0) * K + aK];
    const float* aPtr1 = &A[(size_t)(mBase + aRow1) * K + aK];

    const float* bPtr0;
    const float* bPtr1;
    size_t bKStride;   // pointer advance per BK in the k direction
    int bRow0 = 0, bRow1 = 0, bK = 0, bKr0 = 0, bKr1 = 0, bCol = 0;
    if (TRANSB) {
        bRow0 = t >> 2;          // n
        bRow1 = bRow0 + 64;
        bK    = (t & 3) * 4;     // k
        bPtr0 = &B[(size_t)(nBase + bRow0) * K + bK];
        bPtr1 = &B[(size_t)(nBase + bRow1) * K + bK];
        bKStride = BK;
    } else {
        bKr0 = t >> 5;           // 0..7  (k)
        bKr1 = bKr0 + 8;         // 8..15
        bCol = (t & 31) * 4;     // n
        bPtr0 = &B[(size_t)bKr0 * N + nBase + bCol];
        bPtr1 = &B[(size_t)bKr1 * N + nBase + bCol];
        bKStride = (size_t)BK * N;
    }

    unsigned long long acc[8][4];
#pragma unroll
    for (int i = 0; i < 8; i++)
#pragma unroll
        for (int j = 0; j < 4; j++) acc[i][j] = 0ULL;

    // ---- prologue: load tile 0 into registers ----
    float4 ra0 = *reinterpret_cast<const float4*>(aPtr0);
    float4 ra1 = *reinterpret_cast<const float4*>(aPtr1);
    float4 rb0 = *reinterpret_cast<const float4*>(bPtr0);
    float4 rb1 = *reinterpret_cast<const float4*>(bPtr1);

    int buf = 0;
    for (int k0 = 0; k0 < K; k0 += BK, buf ^= 1) {
        // ---- commit staged registers to SMEM buffer `buf` ----
        As[buf][aK + 0][aRow0] = ra0.x;
        As[buf][aK + 1][aRow0] = ra0.y;
        As[buf][aK + 2][aRow0] = ra0.z;
        As[buf][aK + 3][aRow0] = ra0.w;
        As[buf][aK + 0][aRow1] = ra1.x;
        As[buf][aK + 1][aRow1] = ra1.y;
        As[buf][aK + 2][aRow1] = ra1.z;
        As[buf][aK + 3][aRow1] = ra1.w;
        if (TRANSB) {
            Bs[buf][bK + 0][bRow0] = rb0.x;
            Bs[buf][bK + 1][bRow0] = rb0.y;
            Bs[buf][bK + 2][bRow0] = rb0.z;
            Bs[buf][bK + 3][bRow0] = rb0.w;
            Bs[buf][bK + 0][bRow1] = rb1.x;
            Bs[buf][bK + 1][bRow1] = rb1.y;
            Bs[buf][bK + 2][bRow1] = rb1.z;
            Bs[buf][bK + 3][bRow1] = rb1.w;
        } else {
            *reinterpret_cast<float4*>(&Bs[buf][bKr0][bCol]) = rb0;
            *reinterpret_cast<float4*>(&Bs[buf][bKr1][bCol]) = rb1;
        }
        __syncthreads();   // single barrier per tile (ping-pong removes tail sync)

        // ---- prefetch next tile (LDGs overlap the compute below) ----
        if (k0 + BK < K) {
            aPtr0 += BK; aPtr1 += BK;
            bPtr0 += bKStride; bPtr1 += bKStride;
            ra0 = *reinterpret_cast<const float4*>(aPtr0);
            ra1 = *reinterpret_cast<const float4*>(aPtr1);
            rb0 = *reinterpret_cast<const float4*>(bPtr0);
            rb1 = *reinterpret_cast<const float4*>(bPtr1);
        }

        // ---- 8x8 outer product per thread, packed f32x2 FMAs ----
#pragma unroll
        for (int kk = 0; kk < BK; kk++) {
            float4 a0 = *reinterpret_cast<const float4*>(&As[buf][kk][ty * 8]);
            float4 a1 = *reinterpret_cast<const float4*>(&As[buf][kk][ty * 8 + 4]);
            unsigned long long b0 =
                *reinterpret_cast<const unsigned long long*>(&Bs[buf][kk][tx * 8 + 0]);
            unsigned long long b1 =
                *reinterpret_cast<const unsigned long long*>(&Bs[buf][kk][tx * 8 + 2]);
            unsigned long long b2 =
                *reinterpret_cast<const unsigned long long*>(&Bs[buf][kk][tx * 8 + 4]);
            unsigned long long b3 =
                *reinterpret_cast<const unsigned long long*>(&Bs[buf][kk][tx * 8 + 6]);

            unsigned long long ad;
            ad = pack_dup(a0.x);
            ffma2(acc[0][0], ad, b0); ffma2(acc[0][1], ad, b1);
            ffma2(acc[0][2], ad, b2); ffma2(acc[0][3], ad, b3);
            ad = pack_dup(a0.y);
            ffma2(acc[1][0], ad, b0); ffma2(acc[1][1], ad, b1);
            ffma2(acc[1][2], ad, b2); ffma2(acc[1][3], ad, b3);
            ad = pack_dup(a0.z);
            ffma2(acc[2][0], ad, b0); ffma2(acc[2][1], ad, b1);
            ffma2(acc[2][2], ad, b2); ffma2(acc[2][3], ad, b3);
            ad = pack_dup(a0.w);
            ffma2(acc[3][0], ad, b0); ffma2(acc[3][1], ad, b1);
            ffma2(acc[3][2], ad, b2); ffma2(acc[3][3], ad, b3);
            ad = pack_dup(a1.x);
            ffma2(acc[4][0], ad, b0); ffma2(acc[4][1], ad, b1);
            ffma2(acc[4][2], ad, b2); ffma2(acc[4][3], ad, b3);
            ad = pack_dup(a1.y);
            ffma2(acc[5][0], ad, b0); ffma2(acc[5][1], ad, b1);
            ffma2(acc[5][2], ad, b2); ffma2(acc[5][3], ad, b3);
            ad = pack_dup(a1.z);
            ffma2(acc[6][0], ad, b0); ffma2(acc[6][1], ad, b1);
            ffma2(acc[6][2], ad, b2); ffma2(acc[6][3], ad, b3);
            ad = pack_dup(a1.w);
            ffma2(acc[7][0], ad, b0); ffma2(acc[7][1], ad, b1);
            ffma2(acc[7][2], ad, b2); ffma2(acc[7][3], ad, b3);
        }
        // no tail barrier: next iteration writes the OTHER buffer; barrier(i+1)
        // proves all warps finished compute(i) before STS(i+2) reuses its buffer.
    }

    // ---- epilogue: scale + pack accumulators to float4 stores ----
#pragma unroll
    for (int i = 0; i < 8; i++) {
        float* cp = &C[(size_t)(mBase + ty * 8 + i) * N + nBase + tx * 8];
#pragma unroll
        for (int j = 0; j < 2; j++) {
            float2 lo = *reinterpret_cast<float2*>(&acc[i][2 * j + 0]);
            float2 hi = *reinterpret_cast<float2*>(&acc[i][2 * j + 1]);
            float4 v = make_float4(lo.x * cScale, lo.y * cScale,
                                   hi.x * cScale, hi.y * cScale);
            *reinterpret_cast<float4*>(cp + 4 * j) = v;
        }
    }
}

// ---------------------------------------------------------------------------
// Row softmax over 4096 columns. One block (256 threads) per row.
// Each thread keeps its 16 elements in registers: load once, write once.
// Input is pre-scaled by 1/32 in the S-GEMM epilogue.
// ---------------------------------------------------------------------------
__global__ __launch_bounds__(256) void softmax_kernel(float* __restrict__ S)
{
    const int row = blockIdx.x;
    const int t   = threadIdx.x;
    float* p = S + (size_t)row * NROWS;

    __shared__ float red[8];

    float4 v[4];
#pragma unroll
    for (int j = 0; j < 4; j++)
        v[j] = *reinterpret_cast<const float4*>(&p[(t + j * 256) * 4]);

    // max reduce
    float m = v[0].x;
#pragma unroll
    for (int j = 0; j < 4; j++) {
        m = fmaxf(m, fmaxf(fmaxf(v[j].x, v[j].y), fmaxf(v[j].z, v[j].w)));
    }
#pragma unroll
    for (int off = 16; off > 0; off >>= 1)
        m = fmaxf(m, __shfl_xor_sync(0xFFFFFFFFu, m, off));
    if ((t & 31) == 0) red[t >> 5] = m;
    __syncthreads();
    if (t < 32) {
        float mm = (t < 8) ? red[t] : -INFINITY;
#pragma unroll
        for (int off = 4; off > 0; off >>= 1)
            mm = fmaxf(mm, __shfl_xor_sync(0xFFFFFFFFu, mm, off));
        if (t == 0) red[0] = mm;
    }
    __syncthreads();
    m = red[0];
    __syncthreads();

    // exp + sum reduce
    float s = 0.0f;
#pragma unroll
    for (int j = 0; j < 4; j++) {
        v[j].x = __expf(v[j].x - m);
        v[j].y = __expf(v[j].y - m);
        v[j].z = __expf(v[j].z - m);
        v[j].w = __expf(v[j].w - m);
        s += (v[j].x + v[j].y) + (v[j].z + v[j].w);
    }
#pragma unroll
    for (int off = 16; off > 0; off >>= 1)
        s += __shfl_xor_sync(0xFFFFFFFFu, s, off);
    if ((t & 31) == 0) red[t >> 5] = s;
    __syncthreads();
    if (t < 32) {
        float ss = (t < 8) ? red[t] : 0.0f;
#pragma unroll
        for (int off = 4; off > 0; off >>= 1)
            ss += __shfl_xor_sync(0xFFFFFFFFu, ss, off);
        if (t == 0) red[0] = ss;
    }
    __syncthreads();
    const float inv = 1.0f / red[0];

#pragma unroll
    for (int j = 0; j < 4; j++) {
        float4 r = v[j];
        r.x *= inv; r.y *= inv; r.z *= inv; r.w *= inv;
        *reinterpret_cast<float4*>(&p[(t + j * 256) * 4]) = r;
    }
}

// ---------------------------------------------------------------------------
// Launch
// ---------------------------------------------------------------------------
extern "C" void kernel_launch(void* const* d_in, const int* in_sizes, int n_in,
                              void* d_out, int out_size)
{
    const float* x  = (const float*)d_in[0];
    const float* Wq = (const float*)d_in[1];
    const float* Wk = (const float*)d_in[2];
    const float* Wv = (const float*)d_in[3];
    float* out = (float*)d_out;

    float *pQ, *pK, *pV, *pS;
    cudaGetSymbolAddress((void**)&pQ, g_Q);
    cudaGetSymbolAddress((void**)&pK, g_K);
    cudaGetSymbolAddress((void**)&pV, g_V);
    cudaGetSymbolAddress((void**)&pS, g_S);

    dim3 blk(256);

    // Fused QKV projections: one launch, grid.z selects {Wq->Q, Wk->K, Wv->V}
    dim3 gProj(DDIM / 128, NROWS / 128, 3);
    sgemm_kernel<false, true><<<gProj, blk>>>(
        x, Wq, Wk, Wv, pQ, pK, pV, NROWS, DDIM, DDIM, 1.0f);

    // Scores: S = (K @ Q^T) / sqrt(1024)  (NT gemm, [4096,4096]; scale folded)
    dim3 gS(NROWS / 128, NROWS / 128, 1);
    sgemm_kernel<true, false><<<gS, blk>>>(
        pK, pQ, nullptr, nullptr, pS, nullptr, nullptr,
        NROWS, NROWS, DDIM, 0.03125f);

    // Row softmax (input already scaled)
    softmax_kernel<<<NROWS, blk>>>(pS);

    // Output: out = P @ V  ([4096,4096] x [4096,1024])
    dim3 gO(DDIM / 128, NROWS / 128, 1);
    sgemm_kernel<false, false><<<gO, blk>>>(
        pS, pV, nullptr, nullptr, out, nullptr, nullptr,
        NROWS, DDIM, NROWS, 1.0f);
}

// round 9
// speedup vs baseline: 1.1758x; 1.1758x over previous
#include <cuda_runtime.h>
#include <math.h>

// Problem constants
#define NROWS 4096
#define DDIM  1024

// Scratch (device-global: no allocation allowed in kernel_launch).
__device__ __align__(16) float g_Q[NROWS * DDIM];
__device__ __align__(16) float g_K[NROWS * DDIM];
__device__ __align__(16) float g_V[NROWS * DDIM];
__device__ __align__(16) float g_S[(size_t)NROWS * NROWS];

// ---------------------------------------------------------------------------
// Packed fp32x2 helpers (Blackwell dual-rate fp32; ptxas never auto-emits)
// ---------------------------------------------------------------------------
__device__ __forceinline__ unsigned long long pack_dup(float a) {
    unsigned long long r;
    asm("mov.b64 %0, {%1, %1};" : "=l"(r) : "f"(a));
    return r;
}
__device__ __forceinline__ unsigned long long pack_pair(float lo, float hi) {
    unsigned long long r;
    asm("mov.b64 %0, {%1, %2};" : "=l"(r) : "f"(lo), "f"(hi));
    return r;
}
__device__ __forceinline__ void ffma2(unsigned long long& c,
                                      unsigned long long a,
                                      unsigned long long b) {
    asm("fma.rn.f32x2 %0, %1, %2, %0;" : "+l"(c) : "l"(a), "l"(b));
}

// ---------------------------------------------------------------------------
// Tiled SGEMM: C[M,N] = cScale * (A[M,K] * B)
//   (B is [K,N] if !TRANSB, [N,K] if TRANSB)
// BM=BN=128, BK=16, 256 threads, 8x8 per thread, f32x2 inner product.
// B-fragment mapping is bank-conflict-free: thread (tx) owns columns
// [4tx, 4tx+4) and [4tx+64, 4tx+68), read as two LDS.128 whose lanes
// cover all 32 banks per phase (vs the naive 8tx mapping's 4-way conflict).
// Double-buffered SMEM (ping-pong): ONE barrier per k-tile; register prefetch
// overlaps global latency with the FMA block.
// MULTI=true: blockIdx.z in {0,1,2} selects (B,C) pair -> fused QKV launch.
// ---------------------------------------------------------------------------
template <bool TRANSB, bool MULTI>
__global__ __launch_bounds__(256, 2) void sgemm_kernel(
    const float* __restrict__ A,
    const float* __restrict__ B0,
    const float* __restrict__ B1,
    const float* __restrict__ B2,
    float* __restrict__ C0,
    float* __restrict__ C1,
    float* __restrict__ C2,
    int M, int N, int K, float cScale)
{
    constexpr int BM = 128, BN = 128, BK = 16;
    __shared__ __align__(16) float As[2][BK][BM];
    __shared__ __align__(16) float Bs[2][BK][BN];

    const float* B = B0;
    float*       C = C0;
    if (MULTI) {
        if (blockIdx.z == 1) { B = B1; C = C1; }
        else if (blockIdx.z == 2) { B = B2; C = C2; }
    }

    const int t  = threadIdx.x;
    const int tx = t & 15;        // 0..15  -> n direction
    const int ty = t >> 4;        // 0..15  -> m direction
    const int mBase = blockIdx.y * BM;
    const int nBase = blockIdx.x * BN;

    // Per-thread staging addresses (constant across k-tiles except k offset)
    const int aRow0 = t >> 2;                 // 0..63
    const int aRow1 = aRow0 + 64;             // 64..127
    const int aK    = (t & 3) * 4;            // 0,4,8,12
    const float* aPtr0 = &A[(size_t)(mBase + aRow0) * K + aK];
    const float* aPtr1 = &A[(size_t)(mBase + aRow1) * K + aK];

    const float* bPtr0;
    const float* bPtr1;
    size_t bKStride;   // pointer advance per BK in the k direction
    int bRow0 = 0, bRow1 = 0, bK = 0, bKr0 = 0, bKr1 = 0, bCol = 0;
    if (TRANSB) {
        bRow0 = t >> 2;          // n
        bRow1 = bRow0 + 64;
        bK    = (t & 3) * 4;     // k
        bPtr0 = &B[(size_t)(nBase + bRow0) * K + bK];
        bPtr1 = &B[(size_t)(nBase + bRow1) * K + bK];
        bKStride = BK;
    } else {
        bKr0 = t >> 5;           // 0..7  (k)
        bKr1 = bKr0 + 8;         // 8..15
        bCol = (t & 31) * 4;     // n
        bPtr0 = &B[(size_t)bKr0 * N + nBase + bCol];
        bPtr1 = &B[(size_t)bKr1 * N + nBase + bCol];
        bKStride = (size_t)BK * N;
    }

    unsigned long long acc[8][4];
#pragma unroll
    for (int i = 0; i < 8; i++)
#pragma unroll
        for (int j = 0; j < 4; j++) acc[i][j] = 0ULL;

    // ---- prologue: load tile 0 into registers ----
    float4 ra0 = *reinterpret_cast<const float4*>(aPtr0);
    float4 ra1 = *reinterpret_cast<const float4*>(aPtr1);
    float4 rb0 = *reinterpret_cast<const float4*>(bPtr0);
    float4 rb1 = *reinterpret_cast<const float4*>(bPtr1);

    int buf = 0;
    for (int k0 = 0; k0 < K; k0 += BK, buf ^= 1) {
        // ---- commit staged registers to SMEM buffer `buf` ----
        As[buf][aK + 0][aRow0] = ra0.x;
        As[buf][aK + 1][aRow0] = ra0.y;
        As[buf][aK + 2][aRow0] = ra0.z;
        As[buf][aK + 3][aRow0] = ra0.w;
        As[buf][aK + 0][aRow1] = ra1.x;
        As[buf][aK + 1][aRow1] = ra1.y;
        As[buf][aK + 2][aRow1] = ra1.z;
        As[buf][aK + 3][aRow1] = ra1.w;
        if (TRANSB) {
            Bs[buf][bK + 0][bRow0] = rb0.x;
            Bs[buf][bK + 1][bRow0] = rb0.y;
            Bs[buf][bK + 2][bRow0] = rb0.z;
            Bs[buf][bK + 3][bRow0] = rb0.w;
            Bs[buf][bK + 0][bRow1] = rb1.x;
            Bs[buf][bK + 1][bRow1] = rb1.y;
            Bs[buf][bK + 2][bRow1] = rb1.z;
            Bs[buf][bK + 3][bRow1] = rb1.w;
        } else {
            *reinterpret_cast<float4*>(&Bs[buf][bKr0][bCol]) = rb0;
            *reinterpret_cast<float4*>(&Bs[buf][bKr1][bCol]) = rb1;
        }
        __syncthreads();   // single barrier per tile (ping-pong removes tail sync)

        // ---- prefetch next tile (LDGs overlap the compute below) ----
        if (k0 + BK < K) {
            aPtr0 += BK; aPtr1 += BK;
            bPtr0 += bKStride; bPtr1 += bKStride;
            ra0 = *reinterpret_cast<const float4*>(aPtr0);
            ra1 = *reinterpret_cast<const float4*>(aPtr1);
            rb0 = *reinterpret_cast<const float4*>(bPtr0);
            rb1 = *reinterpret_cast<const float4*>(bPtr1);
        }

        // ---- 8x8 outer product per thread, packed f32x2 FMAs ----
        // B fragment: cols [4tx,4tx+4) + [4tx+64,4tx+68): two LDS.128,
        // lanes 0..7 span all 32 banks per phase -> conflict-free.
#pragma unroll
        for (int kk = 0; kk < BK; kk++) {
            float4 a0 = *reinterpret_cast<const float4*>(&As[buf][kk][ty * 8]);
            float4 a1 = *reinterpret_cast<const float4*>(&As[buf][kk][ty * 8 + 4]);
            float4 bq0 = *reinterpret_cast<const float4*>(&Bs[buf][kk][tx * 4]);
            float4 bq1 = *reinterpret_cast<const float4*>(&Bs[buf][kk][tx * 4 + 64]);

            unsigned long long b0 = pack_pair(bq0.x, bq0.y);
            unsigned long long b1 = pack_pair(bq0.z, bq0.w);
            unsigned long long b2 = pack_pair(bq1.x, bq1.y);
            unsigned long long b3 = pack_pair(bq1.z, bq1.w);

            unsigned long long ad;
            ad = pack_dup(a0.x);
            ffma2(acc[0][0], ad, b0); ffma2(acc[0][1], ad, b1);
            ffma2(acc[0][2], ad, b2); ffma2(acc[0][3], ad, b3);
            ad = pack_dup(a0.y);
            ffma2(acc[1][0], ad, b0); ffma2(acc[1][1], ad, b1);
            ffma2(acc[1][2], ad, b2); ffma2(acc[1][3], ad, b3);
            ad = pack_dup(a0.z);
            ffma2(acc[2][0], ad, b0); ffma2(acc[2][1], ad, b1);
            ffma2(acc[2][2], ad, b2); ffma2(acc[2][3], ad, b3);
            ad = pack_dup(a0.w);
            ffma2(acc[3][0], ad, b0); ffma2(acc[3][1], ad, b1);
            ffma2(acc[3][2], ad, b2); ffma2(acc[3][3], ad, b3);
            ad = pack_dup(a1.x);
            ffma2(acc[4][0], ad, b0); ffma2(acc[4][1], ad, b1);
            ffma2(acc[4][2], ad, b2); ffma2(acc[4][3], ad, b3);
            ad = pack_dup(a1.y);
            ffma2(acc[5][0], ad, b0); ffma2(acc[5][1], ad, b1);
            ffma2(acc[5][2], ad, b2); ffma2(acc[5][3], ad, b3);
            ad = pack_dup(a1.z);
            ffma2(acc[6][0], ad, b0); ffma2(acc[6][1], ad, b1);
            ffma2(acc[6][2], ad, b2); ffma2(acc[6][3], ad, b3);
            ad = pack_dup(a1.w);
            ffma2(acc[7][0], ad, b0); ffma2(acc[7][1], ad, b1);
            ffma2(acc[7][2], ad, b2); ffma2(acc[7][3], ad, b3);
        }
        // no tail barrier: next iteration writes the OTHER buffer; barrier(i+1)
        // proves all warps finished compute(i) before STS(i+2) reuses its buffer.
    }

    // ---- epilogue: scale + pack accumulators to float4 stores ----
    // Thread's columns: [nBase+4tx, +4) from acc[i][0..1], [nBase+4tx+64, +4)
    // from acc[i][2..3].
#pragma unroll
    for (int i = 0; i < 8; i++) {
        float* cp = &C[(size_t)(mBase + ty * 8 + i) * N + nBase + tx * 4];
        {
            float2 lo = *reinterpret_cast<float2*>(&acc[i][0]);
            float2 hi = *reinterpret_cast<float2*>(&acc[i][1]);
            float4 v = make_float4(lo.x * cScale, lo.y * cScale,
                                   hi.x * cScale, hi.y * cScale);
            *reinterpret_cast<float4*>(cp) = v;
        }
        {
            float2 lo = *reinterpret_cast<float2*>(&acc[i][2]);
            float2 hi = *reinterpret_cast<float2*>(&acc[i][3]);
            float4 v = make_float4(lo.x * cScale, lo.y * cScale,
                                   hi.x * cScale, hi.y * cScale);
            *reinterpret_cast<float4*>(cp + 64) = v;
        }
    }
}

// ---------------------------------------------------------------------------
// Row softmax over 4096 columns. One block (256 threads) per row.
// Each thread keeps its 16 elements in registers: load once, write once.
// Input is pre-scaled by 1/32 in the S-GEMM epilogue.
// ---------------------------------------------------------------------------
__global__ __launch_bounds__(256) void softmax_kernel(float* __restrict__ S)
{
    const int row = blockIdx.x;
    const int t   = threadIdx.x;
    float* p = S + (size_t)row * NROWS;

    __shared__ float red[8];

    float4 v[4];
#pragma unroll
    for (int j = 0; j < 4; j++)
        v[j] = *reinterpret_cast<const float4*>(&p[(t + j * 256) * 4]);

    // max reduce
    float m = v[0].x;
#pragma unroll
    for (int j = 0; j < 4; j++) {
        m = fmaxf(m, fmaxf(fmaxf(v[j].x, v[j].y), fmaxf(v[j].z, v[j].w)));
    }
#pragma unroll
    for (int off = 16; off > 0; off >>= 1)
        m = fmaxf(m, __shfl_xor_sync(0xFFFFFFFFu, m, off));
    if ((t & 31) == 0) red[t >> 5] = m;
    __syncthreads();
    if (t < 32) {
        float mm = (t < 8) ? red[t] : -INFINITY;
#pragma unroll
        for (int off = 4; off > 0; off >>= 1)
            mm = fmaxf(mm, __shfl_xor_sync(0xFFFFFFFFu, mm, off));
        if (t == 0) red[0] = mm;
    }
    __syncthreads();
    m = red[0];
    __syncthreads();

    // exp + sum reduce
    float s = 0.0f;
#pragma unroll
    for (int j = 0; j < 4; j++) {
        v[j].x = __expf(v[j].x - m);
        v[j].y = __expf(v[j].y - m);
        v[j].z = __expf(v[j].z - m);
        v[j].w = __expf(v[j].w - m);
        s += (v[j].x + v[j].y) + (v[j].z + v[j].w);
    }
#pragma unroll
    for (int off = 16; off > 0; off >>= 1)
        s += __shfl_xor_sync(0xFFFFFFFFu, s, off);
    if ((t & 31) == 0) red[t >> 5] = s;
    __syncthreads();
    if (t < 32) {
        float ss = (t < 8) ? red[t] : 0.0f;
#pragma unroll
        for (int off = 4; off > 0; off >>= 1)
            ss += __shfl_xor_sync(0xFFFFFFFFu, ss, off);
        if (t == 0) red[0] = ss;
    }
    __syncthreads();
    const float inv = 1.0f / red[0];

#pragma unroll
    for (int j = 0; j < 4; j++) {
        float4 r = v[j];
        r.x *= inv; r.y *= inv; r.z *= inv; r.w *= inv;
        *reinterpret_cast<float4*>(&p[(t + j * 256) * 4]) = r;
    }
}

// ---------------------------------------------------------------------------
// Launch
// ---------------------------------------------------------------------------
extern "C" void kernel_launch(void* const* d_in, const int* in_sizes, int n_in,
                              void* d_out, int out_size)
{
    const float* x  = (const float*)d_in[0];
    const float* Wq = (const float*)d_in[1];
    const float* Wk = (const float*)d_in[2];
    const float* Wv = (const float*)d_in[3];
    float* out = (float*)d_out;

    float *pQ, *pK, *pV, *pS;
    cudaGetSymbolAddress((void**)&pQ, g_Q);
    cudaGetSymbolAddress((void**)&pK, g_K);
    cudaGetSymbolAddress((void**)&pV, g_V);
    cudaGetSymbolAddress((void**)&pS, g_S);

    dim3 blk(256);

    // Fused QKV projections: one launch, grid.z selects {Wq->Q, Wk->K, Wv->V}
    dim3 gProj(DDIM / 128, NROWS / 128, 3);
    sgemm_kernel<false, true><<<gProj, blk>>>(
        x, Wq, Wk, Wv, pQ, pK, pV, NROWS, DDIM, DDIM, 1.0f);

    // Scores: S = (K @ Q^T) / sqrt(1024)  (NT gemm, [4096,4096]; scale folded)
    dim3 gS(NROWS / 128, NROWS / 128, 1);
    sgemm_kernel<true, false><<<gS, blk>>>(
        pK, pQ, nullptr, nullptr, pS, nullptr, nullptr,
        NROWS, NROWS, DDIM, 0.03125f);

    // Row softmax (input already scaled)
    softmax_kernel<<<NROWS, blk>>>(pS);

    // Output: out = P @ V  ([4096,4096] x [4096,1024])
    dim3 gO(DDIM / 128, NROWS / 128, 1);
    sgemm_kernel<false, false><<<gO, blk>>>(
        pS, pV, nullptr, nullptr, out, nullptr, nullptr,
        NROWS, DDIM, NROWS, 1.0f);
}